// round 3
// baseline (speedup 1.0000x reference)
#include <cuda_runtime.h>
#include <math.h>

#define Bc  8
#define Lc  1024
#define Dc  1024
#define Hc  16
#define HDc 64
#define BHc (Bc*Hc)   // 128
#define Mc  (Bc*Lc)   // 8192

// Scratch (allocation-free rule: __device__ globals)
__device__ float g_q [BHc*Lc*HDc];
__device__ float g_k [BHc*Lc*HDc];
__device__ float g_v [BHc*Lc*HDc];
__device__ float g_q2[BHc*Lc*HDc];
__device__ float g_k2[BHc*Lc*HDc];
__device__ float g_s [134217728];   // B*H*L*L scores/probs (512MB)

// ---------------------------------------------------------------------------
// Kernel 1: fused projections. grid = (8, 64, 5), block = 256.
// C[m][n] = A[m][:] @ W[:][n] + bias[n], scattered to [B,H,L,HD] layout.
// ---------------------------------------------------------------------------
__global__ __launch_bounds__(256) void proj_kernel(
    const float* __restrict__ hidden, const float* __restrict__ source,
    const float* __restrict__ Wq,  const float* __restrict__ bq,
    const float* __restrict__ Wk,  const float* __restrict__ bk,
    const float* __restrict__ Wv,  const float* __restrict__ bv,
    const float* __restrict__ Wq2, const float* __restrict__ bq2,
    const float* __restrict__ Wk2, const float* __restrict__ bk2)
{
    __shared__ __align__(16) float As[16][128];
    __shared__ __align__(16) float Bs[16][128];

    int w = blockIdx.z;
    const float* A = (w == 4) ? source : hidden;
    const float* W; const float* bias; float* out;
    if (w == 0)      { W = Wq;  bias = bq;  out = g_q;  }
    else if (w == 1) { W = Wk;  bias = bk;  out = g_k;  }
    else if (w == 2) { W = Wv;  bias = bv;  out = g_v;  }
    else if (w == 3) { W = Wq2; bias = bq2; out = g_q2; }
    else             { W = Wk2; bias = bk2; out = g_k2; }

    int mBase = blockIdx.y * 128;
    int nBase = blockIdx.x * 128;
    int tid = threadIdx.x;
    int tx = tid & 15, ty = tid >> 4;

    float acc[8][8];
    #pragma unroll
    for (int i = 0; i < 8; i++)
        #pragma unroll
        for (int j = 0; j < 8; j++) acc[i][j] = 0.f;

    for (int k0 = 0; k0 < Dc; k0 += 16) {
        #pragma unroll
        for (int i = 0; i < 2; i++) {
            int lin = tid + i * 256;
            int r  = lin >> 2;
            int c4 = (lin & 3) << 2;
            float4 va = *(const float4*)&A[(size_t)(mBase + r) * Dc + k0 + c4];
            As[c4+0][r] = va.x; As[c4+1][r] = va.y; As[c4+2][r] = va.z; As[c4+3][r] = va.w;
            int rb = lin >> 5;
            int cb = (lin & 31) << 2;
            *(float4*)&Bs[rb][cb] = *(const float4*)&W[(size_t)(k0 + rb) * Dc + nBase + cb];
        }
        __syncthreads();
        #pragma unroll
        for (int kk = 0; kk < 16; kk++) {
            float a[8], bb[8];
            float4 t;
            t = *(const float4*)&As[kk][ty*4];      a[0]=t.x; a[1]=t.y; a[2]=t.z; a[3]=t.w;
            t = *(const float4*)&As[kk][64+ty*4];   a[4]=t.x; a[5]=t.y; a[6]=t.z; a[7]=t.w;
            t = *(const float4*)&Bs[kk][tx*4];      bb[0]=t.x; bb[1]=t.y; bb[2]=t.z; bb[3]=t.w;
            t = *(const float4*)&Bs[kk][64+tx*4];   bb[4]=t.x; bb[5]=t.y; bb[6]=t.z; bb[7]=t.w;
            #pragma unroll
            for (int i = 0; i < 8; i++)
                #pragma unroll
                for (int j = 0; j < 8; j++) acc[i][j] += a[i] * bb[j];
        }
        __syncthreads();
    }

    // Epilogue: n -> (head, hd). nBase multiple of 128 => col groups map to heads h0, h0+1.
    int h0 = nBase >> 6;
    float4 b0 = *(const float4*)&bias[nBase + tx*4];
    float4 b1 = *(const float4*)&bias[nBase + 64 + tx*4];
    #pragma unroll
    for (int i = 0; i < 8; i++) {
        int row = (i < 4) ? (ty*4 + i) : (64 + ty*4 + (i - 4));
        int m = mBase + row;
        int b_ = m >> 10, l = m & 1023;
        float4 o0 = make_float4(acc[i][0]+b0.x, acc[i][1]+b0.y, acc[i][2]+b0.z, acc[i][3]+b0.w);
        float4 o1 = make_float4(acc[i][4]+b1.x, acc[i][5]+b1.y, acc[i][6]+b1.z, acc[i][7]+b1.w);
        *(float4*)&out[(size_t)((b_*Hc + h0    ) * Lc + l) * HDc + tx*4] = o0;
        *(float4*)&out[(size_t)((b_*Hc + h0 + 1) * Lc + l) * HDc + tx*4] = o1;
    }
}

// ---------------------------------------------------------------------------
// Kernel 2: scores. grid = (8, 8, 128), block = 256.
// S[bh][m][n] = (Q[m]·K[n] + Q2[m]·K2[n]) * scale + mask[b][n]
// ---------------------------------------------------------------------------
__global__ __launch_bounds__(256) void scores_kernel(const float* __restrict__ mask)
{
    __shared__ __align__(16) float As[16][128];
    __shared__ __align__(16) float Bs[16][128];

    int bh = blockIdx.z;
    int b_ = bh >> 4;
    const float* Q  = g_q  + (size_t)bh * Lc * HDc;
    const float* Km = g_k  + (size_t)bh * Lc * HDc;
    const float* Q2 = g_q2 + (size_t)bh * Lc * HDc;
    const float* K2 = g_k2 + (size_t)bh * Lc * HDc;
    float* S = g_s + (size_t)bh * Lc * Lc;

    int mBase = blockIdx.y * 128, nBase = blockIdx.x * 128;
    int tid = threadIdx.x, tx = tid & 15, ty = tid >> 4;

    float acc[8][8];
    #pragma unroll
    for (int i = 0; i < 8; i++)
        #pragma unroll
        for (int j = 0; j < 8; j++) acc[i][j] = 0.f;

    #pragma unroll
    for (int phase = 0; phase < 2; phase++) {
        const float* Ap = phase ? Q2 : Q;
        const float* Bp = phase ? K2 : Km;
        for (int k0 = 0; k0 < HDc; k0 += 16) {
            #pragma unroll
            for (int i = 0; i < 2; i++) {
                int lin = tid + i * 256;
                int r  = lin >> 2;
                int c4 = (lin & 3) << 2;
                float4 va = *(const float4*)&Ap[(size_t)(mBase + r) * HDc + k0 + c4];
                As[c4+0][r] = va.x; As[c4+1][r] = va.y; As[c4+2][r] = va.z; As[c4+3][r] = va.w;
                float4 vb = *(const float4*)&Bp[(size_t)(nBase + r) * HDc + k0 + c4];
                Bs[c4+0][r] = vb.x; Bs[c4+1][r] = vb.y; Bs[c4+2][r] = vb.z; Bs[c4+3][r] = vb.w;
            }
            __syncthreads();
            #pragma unroll
            for (int kk = 0; kk < 16; kk++) {
                float a[8], bb[8];
                float4 t;
                t = *(const float4*)&As[kk][ty*4];      a[0]=t.x; a[1]=t.y; a[2]=t.z; a[3]=t.w;
                t = *(const float4*)&As[kk][64+ty*4];   a[4]=t.x; a[5]=t.y; a[6]=t.z; a[7]=t.w;
                t = *(const float4*)&Bs[kk][tx*4];      bb[0]=t.x; bb[1]=t.y; bb[2]=t.z; bb[3]=t.w;
                t = *(const float4*)&Bs[kk][64+tx*4];   bb[4]=t.x; bb[5]=t.y; bb[6]=t.z; bb[7]=t.w;
                #pragma unroll
                for (int i = 0; i < 8; i++)
                    #pragma unroll
                    for (int j = 0; j < 8; j++) acc[i][j] += a[i] * bb[j];
            }
            __syncthreads();
        }
    }

    const float scale = 0.125f;   // 1/sqrt(64)
    float4 mk0 = *(const float4*)&mask[b_*Lc + nBase + tx*4];
    float4 mk1 = *(const float4*)&mask[b_*Lc + nBase + 64 + tx*4];
    #pragma unroll
    for (int i = 0; i < 8; i++) {
        int row = (i < 4) ? (ty*4 + i) : (64 + ty*4 + (i - 4));
        int m = mBase + row;
        float4 s0 = make_float4(acc[i][0]*scale + mk0.x, acc[i][1]*scale + mk0.y,
                                acc[i][2]*scale + mk0.z, acc[i][3]*scale + mk0.w);
        float4 s1 = make_float4(acc[i][4]*scale + mk1.x, acc[i][5]*scale + mk1.y,
                                acc[i][6]*scale + mk1.z, acc[i][7]*scale + mk1.w);
        *(float4*)&S[(size_t)m * Lc + nBase + tx*4]      = s0;
        *(float4*)&S[(size_t)m * Lc + nBase + 64 + tx*4] = s1;
    }
}

// ---------------------------------------------------------------------------
// Kernel 3: in-place softmax over rows of 1024. grid = 131072, block = 256.
// ---------------------------------------------------------------------------
__global__ __launch_bounds__(256) void softmax_kernel()
{
    size_t row = blockIdx.x;
    float* p = g_s + row * Lc;
    int tid = threadIdx.x;
    int lane = tid & 31, wid = tid >> 5;
    __shared__ float red[8];

    float4 v = *(float4*)&p[tid * 4];
    float m = fmaxf(fmaxf(v.x, v.y), fmaxf(v.z, v.w));
    #pragma unroll
    for (int o = 16; o > 0; o >>= 1) m = fmaxf(m, __shfl_xor_sync(0xffffffffu, m, o));
    if (lane == 0) red[wid] = m;
    __syncthreads();
    if (tid == 0) {
        float mm = red[0];
        #pragma unroll
        for (int i = 1; i < 8; i++) mm = fmaxf(mm, red[i]);
        red[0] = mm;
    }
    __syncthreads();
    m = red[0];
    __syncthreads();

    v.x = expf(v.x - m); v.y = expf(v.y - m);
    v.z = expf(v.z - m); v.w = expf(v.w - m);
    float s = v.x + v.y + v.z + v.w;
    #pragma unroll
    for (int o = 16; o > 0; o >>= 1) s += __shfl_xor_sync(0xffffffffu, s, o);
    if (lane == 0) red[wid] = s;
    __syncthreads();
    if (tid == 0) {
        float ss = red[0];
        #pragma unroll
        for (int i = 1; i < 8; i++) ss += red[i];
        red[0] = ss;
    }
    __syncthreads();
    float inv = 1.f / red[0];
    v.x *= inv; v.y *= inv; v.z *= inv; v.w *= inv;
    *(float4*)&p[tid * 4] = v;
}

// ---------------------------------------------------------------------------
// Kernel 4: ctx = P @ V, write [B,L,D]. grid = (1, 8, 128), block = 256.
// ---------------------------------------------------------------------------
__global__ __launch_bounds__(256) void pv_kernel(float* __restrict__ out)
{
    __shared__ __align__(16) float Ps[16][128];
    __shared__ __align__(16) float Vs[16][64];

    int bh = blockIdx.z;
    int b_ = bh >> 4, h = bh & 15;
    const float* P = g_s + (size_t)bh * Lc * Lc;
    const float* V = g_v + (size_t)bh * Lc * HDc;
    int mBase = blockIdx.y * 128;
    int tid = threadIdx.x, tx = tid & 15, ty = tid >> 4;

    float acc[8][4];
    #pragma unroll
    for (int i = 0; i < 8; i++)
        #pragma unroll
        for (int j = 0; j < 4; j++) acc[i][j] = 0.f;

    for (int k0 = 0; k0 < Lc; k0 += 16) {
        #pragma unroll
        for (int i = 0; i < 2; i++) {
            int lin = tid + i * 256;
            int r  = lin >> 2;
            int c4 = (lin & 3) << 2;
            float4 vp = *(const float4*)&P[(size_t)(mBase + r) * Lc + k0 + c4];
            Ps[c4+0][r] = vp.x; Ps[c4+1][r] = vp.y; Ps[c4+2][r] = vp.z; Ps[c4+3][r] = vp.w;
        }
        {
            int r = tid >> 4, c4 = (tid & 15) << 2;
            *(float4*)&Vs[r][c4] = *(const float4*)&V[(size_t)(k0 + r) * HDc + c4];
        }
        __syncthreads();
        #pragma unroll
        for (int kk = 0; kk < 16; kk++) {
            float a[8];
            float4 t;
            t = *(const float4*)&Ps[kk][ty*4];     a[0]=t.x; a[1]=t.y; a[2]=t.z; a[3]=t.w;
            t = *(const float4*)&Ps[kk][64+ty*4];  a[4]=t.x; a[5]=t.y; a[6]=t.z; a[7]=t.w;
            float4 bv4 = *(const float4*)&Vs[kk][tx*4];
            float bb[4] = {bv4.x, bv4.y, bv4.z, bv4.w};
            #pragma unroll
            for (int i = 0; i < 8; i++)
                #pragma unroll
                for (int j = 0; j < 4; j++) acc[i][j] += a[i] * bb[j];
        }
        __syncthreads();
    }

    #pragma unroll
    for (int i = 0; i < 8; i++) {
        int row = (i < 4) ? (ty*4 + i) : (64 + ty*4 + (i - 4));
        int l = mBase + row;
        float4 o = make_float4(acc[i][0], acc[i][1], acc[i][2], acc[i][3]);
        *(float4*)&out[(size_t)(b_*Lc + l) * Dc + h*HDc + tx*4] = o;
    }
}

// ---------------------------------------------------------------------------
extern "C" void kernel_launch(void* const* d_in, const int* in_sizes, int n_in,
                              void* d_out, int out_size)
{
    (void)in_sizes; (void)n_in; (void)out_size;
    const float* hidden = (const float*)d_in[0];
    const float* mask   = (const float*)d_in[1];
    const float* source = (const float*)d_in[2];
    const float* Wq  = (const float*)d_in[3];  const float* bq  = (const float*)d_in[4];
    const float* Wk  = (const float*)d_in[5];  const float* bk  = (const float*)d_in[6];
    const float* Wv  = (const float*)d_in[7];  const float* bv  = (const float*)d_in[8];
    const float* Wq2 = (const float*)d_in[9];  const float* bq2 = (const float*)d_in[10];
    const float* Wk2 = (const float*)d_in[11]; const float* bk2 = (const float*)d_in[12];
    float* out = (float*)d_out;

    dim3 g1(8, 64, 5);
    proj_kernel<<<g1, 256>>>(hidden, source, Wq, bq, Wk, bk, Wv, bv, Wq2, bq2, Wk2, bk2);
    dim3 g2(8, 8, 128);
    scores_kernel<<<g2, 256>>>(mask);
    softmax_kernel<<<131072, 256>>>();
    dim3 g4(1, 8, 128);
    pv_kernel<<<g4, 256>>>(out);
}